// round 8
// baseline (speedup 1.0000x reference)
#include <cuda_runtime.h>
#include <cstdint>

// WindowAttention: B=4096 windows, N=64 tokens, C=128 dim, fp32.
// One CTA per window, 256 threads (8 warps), 2x4 warp grid of 32x32 tiles
// (32x16 for the S GEMM). mma.m16n8k8 tf32, plain smem layouts.
// R7: explicit software-pipelined fragment loads (double-buffered regs)
// in all four GEMM mainloops. Weight staging after acc death (R6).

#define PX 132   // X/Q/K pitch: A-frag bank 4g+t (conflict-free)
#define PV 136   // V pitch:     B-frag bank 8t+g (conflict-free)
#define PS 68    // S pitch:     A-frag bank 4g+t
#define PW 136   // W pitch:     B-frag bank 8t+g

#define OFF_X  0
#define OFF_Q  (64*PX)
#define OFF_K  (2*64*PX)
#define OFF_V  (3*64*PX)
#define OFF_W  (3*64*PX + 64*PV)   // 34048
#define OFF_S  OFF_W               // S aliases W (dead in between)
#define OFF_PM (OFF_W + 64*PS)     // softmax partials inside W region
#define SMEM_FLOATS (OFF_W + 128*PW)   // 51456
#define SMEM_BYTES  (SMEM_FLOATS * 4)  // 205824

__device__ __forceinline__ float tf32f(float x) {
    uint32_t u;
    asm("cvt.rna.tf32.f32 %0, %1;" : "=r"(u) : "f"(x));
    return __uint_as_float(u);
}

__device__ __forceinline__ void mma8(float acc[4],
                                     uint32_t a0, uint32_t a1, uint32_t a2, uint32_t a3,
                                     uint32_t b0, uint32_t b1) {
    asm volatile(
        "mma.sync.aligned.m16n8k8.row.col.f32.tf32.tf32.f32 "
        "{%0,%1,%2,%3}, {%4,%5,%6,%7}, {%8,%9}, {%0,%1,%2,%3};\n"
        : "+f"(acc[0]), "+f"(acc[1]), "+f"(acc[2]), "+f"(acc[3])
        : "r"(a0), "r"(a1), "r"(a2), "r"(a3), "r"(b0), "r"(b1));
}

__device__ __forceinline__ void bargrp(int id) {
    asm volatile("bar.sync %0, 128;" :: "r"(id) : "memory");
}

__global__ void __launch_bounds__(256, 1)
win_attn_kernel(const float* __restrict__ x,
                const float* __restrict__ wqkv,
                const float* __restrict__ bqkv,
                const float* __restrict__ wproj,
                const float* __restrict__ bproj,
                float* __restrict__ out)
{
    extern __shared__ float smem[];
    float* Xs = smem + OFF_X;
    float* Qs = smem + OFF_Q;   // reused for O
    float* Ks = smem + OFF_K;
    float* Vs = smem + OFF_V;
    float* Ws = smem + OFF_W;
    float* Ss = smem + OFF_S;
    float* Pm = smem + OFF_PM;

    const int tid   = threadIdx.x;
    const int warp  = tid >> 5;
    const int lane  = tid & 31;
    const int g     = lane >> 2;
    const int t     = lane & 3;
    const int wr    = warp & 1;        // 32-row group
    const int wc    = warp >> 1;       // 0..3: 32-col group
    const int mrow  = wr * 32;
    const int nbase = wc * 32;

    const float* xw = x + (size_t)blockIdx.x * 64 * 128;

    // ---------- prologue: X -> smem, W chunk0 -> smem ----------
    #pragma unroll
    for (int s = 0; s < 8; ++s) {
        int i = tid + s * 256;
        float4 v = *(const float4*)(xw + (i >> 5) * 128 + ((i & 31) << 2));
        float* d = Xs + (i >> 5) * PX + ((i & 31) << 2);
        d[0] = tf32f(v.x); d[1] = tf32f(v.y); d[2] = tf32f(v.z); d[3] = tf32f(v.w);
    }
    #pragma unroll
    for (int s = 0; s < 16; ++s) {
        int i = tid + s * 256;
        float4 v = *(const float4*)(wqkv + (i >> 5) * 384 + ((i & 31) << 2));
        float* d = Ws + (i >> 5) * PW + ((i & 31) << 2);
        d[0] = tf32f(v.x); d[1] = tf32f(v.y); d[2] = tf32f(v.z); d[3] = tf32f(v.w);
    }
    __syncthreads();

    // ============ GEMM1: QKV = X @ Wqkv + b, 3 chunks of 128 cols ============
    #pragma unroll
    for (int c = 0; c < 3; ++c) {
        float acc[2][4][4];
        #pragma unroll
        for (int m = 0; m < 2; ++m)
            #pragma unroll
            for (int n = 0; n < 4; ++n)
                acc[m][n][0] = acc[m][n][1] = acc[m][n][2] = acc[m][n][3] = 0.f;

        {   // pipelined mainloop: 16 k-steps, prefetch depth 1
            const float* xr0 = Xs + (mrow + g) * PX + t;
            const float* xr1 = xr0 + 16 * PX;
            const float* wrp = Ws + t * PW + nbase + g;

            uint32_t Af[2][8], Bf[2][8];
            Af[0][0] = __float_as_uint(xr0[0]);
            Af[0][1] = __float_as_uint(xr0[8 * PX]);
            Af[0][2] = __float_as_uint(xr0[4]);
            Af[0][3] = __float_as_uint(xr0[8 * PX + 4]);
            Af[0][4] = __float_as_uint(xr1[0]);
            Af[0][5] = __float_as_uint(xr1[8 * PX]);
            Af[0][6] = __float_as_uint(xr1[4]);
            Af[0][7] = __float_as_uint(xr1[8 * PX + 4]);
            #pragma unroll
            for (int nt = 0; nt < 4; ++nt) {
                Bf[0][2 * nt]     = __float_as_uint(wrp[nt * 8]);
                Bf[0][2 * nt + 1] = __float_as_uint(wrp[4 * PW + nt * 8]);
            }

            #pragma unroll
            for (int ks = 0; ks < 16; ++ks) {
                const int cur = ks & 1, nxt = cur ^ 1;
                if (ks < 15) {
                    const float* x0 = xr0 + (ks + 1) * 8;
                    const float* x1 = xr1 + (ks + 1) * 8;
                    const float* wp = wrp + (ks + 1) * 8 * PW;
                    Af[nxt][0] = __float_as_uint(x0[0]);
                    Af[nxt][1] = __float_as_uint(x0[8 * PX]);
                    Af[nxt][2] = __float_as_uint(x0[4]);
                    Af[nxt][3] = __float_as_uint(x0[8 * PX + 4]);
                    Af[nxt][4] = __float_as_uint(x1[0]);
                    Af[nxt][5] = __float_as_uint(x1[8 * PX]);
                    Af[nxt][6] = __float_as_uint(x1[4]);
                    Af[nxt][7] = __float_as_uint(x1[8 * PX + 4]);
                    #pragma unroll
                    for (int nt = 0; nt < 4; ++nt) {
                        Bf[nxt][2 * nt]     = __float_as_uint(wp[nt * 8]);
                        Bf[nxt][2 * nt + 1] = __float_as_uint(wp[4 * PW + nt * 8]);
                    }
                }
                #pragma unroll
                for (int nt = 0; nt < 4; ++nt) {
                    mma8(acc[0][nt], Af[cur][0], Af[cur][1], Af[cur][2], Af[cur][3],
                         Bf[cur][2 * nt], Bf[cur][2 * nt + 1]);
                    mma8(acc[1][nt], Af[cur][4], Af[cur][5], Af[cur][6], Af[cur][7],
                         Bf[cur][2 * nt], Bf[cur][2 * nt + 1]);
                }
            }
        }

        // epilogue: +bias, tf32-round, scatter to Q/K/V  (acc dies here)
        float* dst = (c == 0) ? Qs : ((c == 1) ? Ks : Vs);
        const int pad = (c == 2) ? PV : PX;
        #pragma unroll
        for (int m = 0; m < 2; ++m) {
            int r0 = mrow + m * 16 + g;
            #pragma unroll
            for (int nt = 0; nt < 4; ++nt) {
                int j = nbase + nt * 8 + 2 * t;
                float b0 = __ldg(bqkv + c * 128 + j);
                float b1 = __ldg(bqkv + c * 128 + j + 1);
                float2 v0 = make_float2(tf32f(acc[m][nt][0] + b0), tf32f(acc[m][nt][1] + b1));
                float2 v1 = make_float2(tf32f(acc[m][nt][2] + b0), tf32f(acc[m][nt][3] + b1));
                *(float2*)&dst[r0 * pad + j]       = v0;
                *(float2*)&dst[(r0 + 8) * pad + j] = v1;
            }
        }

        if (c < 2) {
            // stage next chunk NOW (accs dead -> short register live range)
            float4 ws4[16];
            #pragma unroll
            for (int s = 0; s < 16; ++s) {
                int i = tid + s * 256;
                ws4[s] = *(const float4*)(wqkv + (i >> 5) * 384 + (c + 1) * 128 + ((i & 31) << 2));
            }
            __syncthreads();      // all warps done reading Ws for this chunk
            #pragma unroll
            for (int s = 0; s < 16; ++s) {
                int i = tid + s * 256;
                float* d = Ws + (i >> 5) * PW + ((i & 31) << 2);
                d[0] = tf32f(ws4[s].x); d[1] = tf32f(ws4[s].y);
                d[2] = tf32f(ws4[s].z); d[3] = tf32f(ws4[s].w);
            }
            __syncthreads();
        } else {
            __syncthreads();      // Ws region released (S will alias it)
        }
    }

    // ============ GEMM2: S = Q @ K^T (32 rows x 16 cols per warp) ============
    float sacc[2][2][4];
    #pragma unroll
    for (int m = 0; m < 2; ++m)
        #pragma unroll
        for (int n = 0; n < 2; ++n)
            sacc[m][n][0] = sacc[m][n][1] = sacc[m][n][2] = sacc[m][n][3] = 0.f;

    const int sbase = wc * 16;
    {   // pipelined mainloop: 16 k-steps
        const float* qr0 = Qs + (mrow + g) * PX + t;
        const float* qr1 = qr0 + 16 * PX;
        const float* kr0 = Ks + (sbase + g) * PX + t;
        const float* kr1 = kr0 + 8 * PX;

        uint32_t Af[2][8], Bf[2][4];
        Af[0][0] = __float_as_uint(qr0[0]);
        Af[0][1] = __float_as_uint(qr0[8 * PX]);
        Af[0][2] = __float_as_uint(qr0[4]);
        Af[0][3] = __float_as_uint(qr0[8 * PX + 4]);
        Af[0][4] = __float_as_uint(qr1[0]);
        Af[0][5] = __float_as_uint(qr1[8 * PX]);
        Af[0][6] = __float_as_uint(qr1[4]);
        Af[0][7] = __float_as_uint(qr1[8 * PX + 4]);
        Bf[0][0] = __float_as_uint(kr0[0]);
        Bf[0][1] = __float_as_uint(kr0[4]);
        Bf[0][2] = __float_as_uint(kr1[0]);
        Bf[0][3] = __float_as_uint(kr1[4]);

        #pragma unroll
        for (int ks = 0; ks < 16; ++ks) {
            const int cur = ks & 1, nxt = cur ^ 1;
            if (ks < 15) {
                const float* q0 = qr0 + (ks + 1) * 8;
                const float* q1 = qr1 + (ks + 1) * 8;
                const float* k0p = kr0 + (ks + 1) * 8;
                const float* k1p = kr1 + (ks + 1) * 8;
                Af[nxt][0] = __float_as_uint(q0[0]);
                Af[nxt][1] = __float_as_uint(q0[8 * PX]);
                Af[nxt][2] = __float_as_uint(q0[4]);
                Af[nxt][3] = __float_as_uint(q0[8 * PX + 4]);
                Af[nxt][4] = __float_as_uint(q1[0]);
                Af[nxt][5] = __float_as_uint(q1[8 * PX]);
                Af[nxt][6] = __float_as_uint(q1[4]);
                Af[nxt][7] = __float_as_uint(q1[8 * PX + 4]);
                Bf[nxt][0] = __float_as_uint(k0p[0]);
                Bf[nxt][1] = __float_as_uint(k0p[4]);
                Bf[nxt][2] = __float_as_uint(k1p[0]);
                Bf[nxt][3] = __float_as_uint(k1p[4]);
            }
            mma8(sacc[0][0], Af[cur][0], Af[cur][1], Af[cur][2], Af[cur][3], Bf[cur][0], Bf[cur][1]);
            mma8(sacc[1][0], Af[cur][4], Af[cur][5], Af[cur][6], Af[cur][7], Bf[cur][0], Bf[cur][1]);
            mma8(sacc[0][1], Af[cur][0], Af[cur][1], Af[cur][2], Af[cur][3], Bf[cur][2], Bf[cur][3]);
            mma8(sacc[1][1], Af[cur][4], Af[cur][5], Af[cur][6], Af[cur][7], Bf[cur][2], Bf[cur][3]);
        }
    }

    // ---------- softmax: each row spans the 4 warps with same wr ----------
    const float scale = 0.08838834764831844f;  // 128^-0.5
    const int bid = 1 + wr;
    float mx[2][2];
    #pragma unroll
    for (int m = 0; m < 2; ++m) {
        mx[m][0] = -1e30f; mx[m][1] = -1e30f;
        #pragma unroll
        for (int n = 0; n < 2; ++n) {
            #pragma unroll
            for (int q = 0; q < 4; ++q) sacc[m][n][q] *= scale;
            mx[m][0] = fmaxf(mx[m][0], fmaxf(sacc[m][n][0], sacc[m][n][1]));
            mx[m][1] = fmaxf(mx[m][1], fmaxf(sacc[m][n][2], sacc[m][n][3]));
        }
    }
    #pragma unroll
    for (int m = 0; m < 2; ++m)
        #pragma unroll
        for (int h = 0; h < 2; ++h) {
            mx[m][h] = fmaxf(mx[m][h], __shfl_xor_sync(0xffffffffu, mx[m][h], 1));
            mx[m][h] = fmaxf(mx[m][h], __shfl_xor_sync(0xffffffffu, mx[m][h], 2));
        }
    if (t == 0) {
        #pragma unroll
        for (int m = 0; m < 2; ++m)
            #pragma unroll
            for (int h = 0; h < 2; ++h)
                Pm[(mrow + m * 16 + h * 8 + g) * 4 + wc] = mx[m][h];
    }
    bargrp(bid);
    #pragma unroll
    for (int m = 0; m < 2; ++m)
        #pragma unroll
        for (int h = 0; h < 2; ++h) {
            const float* pr = Pm + (mrow + m * 16 + h * 8 + g) * 4;
            mx[m][h] = fmaxf(fmaxf(pr[0], pr[1]), fmaxf(pr[2], pr[3]));
        }

    float sm[2][2] = {{0.f, 0.f}, {0.f, 0.f}};
    #pragma unroll
    for (int m = 0; m < 2; ++m)
        #pragma unroll
        for (int n = 0; n < 2; ++n) {
            sacc[m][n][0] = __expf(sacc[m][n][0] - mx[m][0]);
            sacc[m][n][1] = __expf(sacc[m][n][1] - mx[m][0]);
            sacc[m][n][2] = __expf(sacc[m][n][2] - mx[m][1]);
            sacc[m][n][3] = __expf(sacc[m][n][3] - mx[m][1]);
            sm[m][0] += sacc[m][n][0] + sacc[m][n][1];
            sm[m][1] += sacc[m][n][2] + sacc[m][n][3];
        }
    #pragma unroll
    for (int m = 0; m < 2; ++m)
        #pragma unroll
        for (int h = 0; h < 2; ++h) {
            sm[m][h] += __shfl_xor_sync(0xffffffffu, sm[m][h], 1);
            sm[m][h] += __shfl_xor_sync(0xffffffffu, sm[m][h], 2);
        }
    if (t == 0) {
        #pragma unroll
        for (int m = 0; m < 2; ++m)
            #pragma unroll
            for (int h = 0; h < 2; ++h)
                Pm[256 + (mrow + m * 16 + h * 8 + g) * 4 + wc] = sm[m][h];
    }
    bargrp(bid);
    float rs[2][2];
    #pragma unroll
    for (int m = 0; m < 2; ++m)
        #pragma unroll
        for (int h = 0; h < 2; ++h) {
            const float* pr = Pm + 256 + (mrow + m * 16 + h * 8 + g) * 4;
            rs[m][h] = 1.f / (pr[0] + pr[1] + pr[2] + pr[3]);
        }

    // P -> S (plain layout, pitch 68)
    #pragma unroll
    for (int m = 0; m < 2; ++m) {
        int r0 = mrow + m * 16 + g;
        #pragma unroll
        for (int nt = 0; nt < 2; ++nt) {
            int j = sbase + nt * 8 + 2 * t;
            float2 v0 = make_float2(tf32f(sacc[m][nt][0] * rs[m][0]),
                                    tf32f(sacc[m][nt][1] * rs[m][0]));
            float2 v1 = make_float2(tf32f(sacc[m][nt][2] * rs[m][1]),
                                    tf32f(sacc[m][nt][3] * rs[m][1]));
            *(float2*)&Ss[r0 * PS + j]       = v0;
            *(float2*)&Ss[(r0 + 8) * PS + j] = v1;
        }
    }
    bargrp(bid);   // this wr-group's S rows complete

    // ============ GEMM3: O = P @ V (32 rows x 32 cols per warp) ============
    float oacc[2][4][4];
    #pragma unroll
    for (int m = 0; m < 2; ++m)
        #pragma unroll
        for (int n = 0; n < 4; ++n)
            oacc[m][n][0] = oacc[m][n][1] = oacc[m][n][2] = oacc[m][n][3] = 0.f;

    {   // pipelined mainloop: 8 k-steps
        const float* pr0 = Ss + (mrow + g) * PS + t;
        const float* pr1 = pr0 + 16 * PS;
        const float* vr  = Vs + t * PV + nbase + g;

        uint32_t Af[2][8], Bf[2][8];
        Af[0][0] = __float_as_uint(pr0[0]);
        Af[0][1] = __float_as_uint(pr0[8 * PS]);
        Af[0][2] = __float_as_uint(pr0[4]);
        Af[0][3] = __float_as_uint(pr0[8 * PS + 4]);
        Af[0][4] = __float_as_uint(pr1[0]);
        Af[0][5] = __float_as_uint(pr1[8 * PS]);
        Af[0][6] = __float_as_uint(pr1[4]);
        Af[0][7] = __float_as_uint(pr1[8 * PS + 4]);
        #pragma unroll
        for (int nt = 0; nt < 4; ++nt) {
            Bf[0][2 * nt]     = __float_as_uint(vr[nt * 8]);
            Bf[0][2 * nt + 1] = __float_as_uint(vr[4 * PV + nt * 8]);
        }

        #pragma unroll
        for (int ks = 0; ks < 8; ++ks) {
            const int cur = ks & 1, nxt = cur ^ 1;
            if (ks < 7) {
                const float* p0 = pr0 + (ks + 1) * 8;
                const float* p1 = pr1 + (ks + 1) * 8;
                const float* vp = vr + (ks + 1) * 8 * PV;
                Af[nxt][0] = __float_as_uint(p0[0]);
                Af[nxt][1] = __float_as_uint(p0[8 * PS]);
                Af[nxt][2] = __float_as_uint(p0[4]);
                Af[nxt][3] = __float_as_uint(p0[8 * PS + 4]);
                Af[nxt][4] = __float_as_uint(p1[0]);
                Af[nxt][5] = __float_as_uint(p1[8 * PS]);
                Af[nxt][6] = __float_as_uint(p1[4]);
                Af[nxt][7] = __float_as_uint(p1[8 * PS + 4]);
                #pragma unroll
                for (int nt = 0; nt < 4; ++nt) {
                    Bf[nxt][2 * nt]     = __float_as_uint(vp[nt * 8]);
                    Bf[nxt][2 * nt + 1] = __float_as_uint(vp[4 * PV + nt * 8]);
                }
            }
            #pragma unroll
            for (int nt = 0; nt < 4; ++nt) {
                mma8(oacc[0][nt], Af[cur][0], Af[cur][1], Af[cur][2], Af[cur][3],
                     Bf[cur][2 * nt], Bf[cur][2 * nt + 1]);
                mma8(oacc[1][nt], Af[cur][4], Af[cur][5], Af[cur][6], Af[cur][7],
                     Bf[cur][2 * nt], Bf[cur][2 * nt + 1]);
            }
        }
    }

    // store O into Qs (Q dead after GEMM2)  -- oacc dies here
    #pragma unroll
    for (int m = 0; m < 2; ++m) {
        int r0 = mrow + m * 16 + g;
        #pragma unroll
        for (int nt = 0; nt < 4; ++nt) {
            int j = nbase + nt * 8 + 2 * t;
            float2 v0 = make_float2(tf32f(oacc[m][nt][0]), tf32f(oacc[m][nt][1]));
            float2 v1 = make_float2(tf32f(oacc[m][nt][2]), tf32f(oacc[m][nt][3]));
            *(float2*)&Qs[r0 * PX + j]       = v0;
            *(float2*)&Qs[(r0 + 8) * PX + j] = v1;
        }
    }

    // stage wproj (short live range: issued after oacc is dead)
    {
        float4 ws4[16];
        #pragma unroll
        for (int s = 0; s < 16; ++s) {
            int i = tid + s * 256;
            ws4[s] = *(const float4*)(wproj + (i >> 5) * 128 + ((i & 31) << 2));
        }
        __syncthreads();           // all S reads + O writes done
        #pragma unroll
        for (int s = 0; s < 16; ++s) {
            int i = tid + s * 256;
            float* d = Ws + (i >> 5) * PW + ((i & 31) << 2);
            d[0] = tf32f(ws4[s].x); d[1] = tf32f(ws4[s].y);
            d[2] = tf32f(ws4[s].z); d[3] = tf32f(ws4[s].w);
        }
        __syncthreads();
    }

    // ============ GEMM4: out = O @ Wproj + b ============
    float acc[2][4][4];
    #pragma unroll
    for (int m = 0; m < 2; ++m)
        #pragma unroll
        for (int n = 0; n < 4; ++n)
            acc[m][n][0] = acc[m][n][1] = acc[m][n][2] = acc[m][n][3] = 0.f;

    {   // pipelined mainloop: 16 k-steps
        const float* or0 = Qs + (mrow + g) * PX + t;
        const float* or1 = or0 + 16 * PX;
        const float* wrp = Ws + t * PW + nbase + g;

        uint32_t Af[2][8], Bf[2][8];
        Af[0][0] = __float_as_uint(or0[0]);
        Af[0][1] = __float_as_uint(or0[8 * PX]);
        Af[0][2] = __float_as_uint(or0[4]);
        Af[0][3] = __float_as_uint(or0[8 * PX + 4]);
        Af[0][4] = __float_as_uint(or1[0]);
        Af[0][5] = __float_as_uint(or1[8 * PX]);
        Af[0][6] = __float_as_uint(or1[4]);
        Af[0][7] = __float_as_uint(or1[8 * PX + 4]);
        #pragma unroll
        for (int nt = 0; nt < 4; ++nt) {
            Bf[0][2 * nt]     = __float_as_uint(wrp[nt * 8]);
            Bf[0][2 * nt + 1] = __float_as_uint(wrp[4 * PW + nt * 8]);
        }

        #pragma unroll
        for (int ks = 0; ks < 16; ++ks) {
            const int cur = ks & 1, nxt = cur ^ 1;
            if (ks < 15) {
                const float* o0 = or0 + (ks + 1) * 8;
                const float* o1 = or1 + (ks + 1) * 8;
                const float* wp = wrp + (ks + 1) * 8 * PW;
                Af[nxt][0] = __float_as_uint(o0[0]);
                Af[nxt][1] = __float_as_uint(o0[8 * PX]);
                Af[nxt][2] = __float_as_uint(o0[4]);
                Af[nxt][3] = __float_as_uint(o0[8 * PX + 4]);
                Af[nxt][4] = __float_as_uint(o1[0]);
                Af[nxt][5] = __float_as_uint(o1[8 * PX]);
                Af[nxt][6] = __float_as_uint(o1[4]);
                Af[nxt][7] = __float_as_uint(o1[8 * PX + 4]);
                #pragma unroll
                for (int nt = 0; nt < 4; ++nt) {
                    Bf[nxt][2 * nt]     = __float_as_uint(wp[nt * 8]);
                    Bf[nxt][2 * nt + 1] = __float_as_uint(wp[4 * PW + nt * 8]);
                }
            }
            #pragma unroll
            for (int nt = 0; nt < 4; ++nt) {
                mma8(acc[0][nt], Af[cur][0], Af[cur][1], Af[cur][2], Af[cur][3],
                     Bf[cur][2 * nt], Bf[cur][2 * nt + 1]);
                mma8(acc[1][nt], Af[cur][4], Af[cur][5], Af[cur][6], Af[cur][7],
                     Bf[cur][2 * nt], Bf[cur][2 * nt + 1]);
            }
        }
    }

    float* outw = out + (size_t)blockIdx.x * 64 * 128;
    #pragma unroll
    for (int m = 0; m < 2; ++m) {
        int r0 = mrow + m * 16 + g;
        #pragma unroll
        for (int nt = 0; nt < 4; ++nt) {
            int j = nbase + nt * 8 + 2 * t;
            float b0 = __ldg(bproj + j);
            float b1 = __ldg(bproj + j + 1);
            *(float2*)(outw + r0 * 128 + j) =
                make_float2(acc[m][nt][0] + b0, acc[m][nt][1] + b1);
            *(float2*)(outw + (r0 + 8) * 128 + j) =
                make_float2(acc[m][nt][2] + b0, acc[m][nt][3] + b1);
        }
    }
}

extern "C" void kernel_launch(void* const* d_in, const int* in_sizes, int n_in,
                              void* d_out, int out_size)
{
    const float* x     = (const float*)d_in[0];
    const float* wqkv  = (const float*)d_in[1];
    const float* bqkv  = (const float*)d_in[2];
    const float* wproj = (const float*)d_in[3];
    const float* bproj = (const float*)d_in[4];
    float* out = (float*)d_out;

    const int nwin = in_sizes[0] / (64 * 128);  // 4096

    cudaFuncSetAttribute(win_attn_kernel,
                         cudaFuncAttributeMaxDynamicSharedMemorySize, SMEM_BYTES);

    win_attn_kernel<<<nwin, 256, SMEM_BYTES>>>(x, wqkv, bqkv, wproj, bproj, out);
}

// round 10
// speedup vs baseline: 1.8754x; 1.8754x over previous
#include <cuda_runtime.h>
#include <cuda_fp16.h>
#include <cstdint>

// WindowAttention: 4096 windows x 64 tokens x 128 dim, fp32 I/O.
// fp16 operands (same 10-bit mantissa as prior tf32 path), fp32 accumulate,
// mma.m16n8k16. 256 thr/CTA, 2x4 warp grid, 32x32 tiles. 2 CTAs/SM.
// Weights pre-transposed to fp16 [n][k] by prep kernel; cp.async staging.
// R10: fix stageW to copy the FULL 32KB chunk (R9 copied only half -> NaN).

#define PXW 68   // X/Q/K/O pitch in 32-bit words (64 half2 + 4 pad)
#define PSW 36   // S pitch (32 half2 + 4 pad)
#define PVW 36   // Vt pitch (channel-major V)
#define PWW 68   // W pitch

#define OFF_X 0
#define OFF_Q (64*PXW)
#define OFF_K (2*64*PXW)
#define OFF_V (3*64*PXW)           // 13056
#define OFF_W (OFF_V + 128*PVW)    // 17664
#define OFF_S OFF_W                // S aliases W
#define OFF_PM (OFF_S + 64*PSW)    // Pm (floats) inside W region
#define SMEM_WORDS (OFF_W + 128*PWW)  // 26368
#define SMEM_BYTES (SMEM_WORDS*4)     // 105472 -> 2 CTAs/SM

__device__ __align__(16) __half g_wqkvT[384*128];
__device__ __align__(16) __half g_wprojT[128*128];

__global__ void prep_w(const float* __restrict__ wqkv, const float* __restrict__ wproj) {
    int n = blockIdx.x, k = threadIdx.x;
    if (n < 384) g_wqkvT[n*128+k] = __float2half_rn(wqkv[k*384+n]);
    else         g_wprojT[(n-384)*128+k] = __float2half_rn(wproj[k*128+(n-384)]);
}

__device__ __forceinline__ uint32_t h2u(float a, float b) {
    __half2 h = __floats2half2_rn(a, b);
    return *reinterpret_cast<uint32_t*>(&h);
}
__device__ __forceinline__ void mma16(float acc[4], uint32_t a0, uint32_t a1,
                                      uint32_t a2, uint32_t a3, uint32_t b0, uint32_t b1) {
    asm volatile(
        "mma.sync.aligned.m16n8k16.row.col.f32.f16.f16.f32 "
        "{%0,%1,%2,%3}, {%4,%5,%6,%7}, {%8,%9}, {%0,%1,%2,%3};\n"
        : "+f"(acc[0]), "+f"(acc[1]), "+f"(acc[2]), "+f"(acc[3])
        : "r"(a0), "r"(a1), "r"(a2), "r"(a3), "r"(b0), "r"(b1));
}
__device__ __forceinline__ void bargrp(int id) {
    asm volatile("bar.sync %0, 128;" :: "r"(id) : "memory");
}
// load 32-row A fragment (2 m16 tiles) at word ptr p (= base + row*pitch + kg*8 + t)
__device__ __forceinline__ void ldA(uint32_t a[8], const uint32_t* p, int pitch) {
    a[0]=p[0]; a[1]=p[8*pitch]; a[2]=p[4]; a[3]=p[8*pitch+4];
    a[4]=p[16*pitch]; a[5]=p[24*pitch]; a[6]=p[16*pitch+4]; a[7]=p[24*pitch+4];
}
// stage full 128x128 fp16 chunk [n][k] -> smem rows pitch PWW, cp.async 16B.
// 2048 quads = 8 iters x 256 threads. (R9 bug: only 4 iters / q&7 -> half chunk.)
__device__ __forceinline__ void stageW(uint32_t* Ww, const __half* __restrict__ src, int tid) {
    uint32_t base = (uint32_t)__cvta_generic_to_shared(Ww);
    #pragma unroll
    for (int it = 0; it < 8; ++it) {
        int idx = tid + it*256, n = idx >> 4, q = idx & 15;
        uint32_t dst = base + (uint32_t)(n*PWW + q*4)*4u;
        asm volatile("cp.async.ca.shared.global [%0], [%1], 16;"
                     :: "r"(dst), "l"(src + n*128 + q*8) : "memory");
    }
    asm volatile("cp.async.commit_group;\n\tcp.async.wait_group 0;" ::: "memory");
}

__global__ void __launch_bounds__(256, 2)
win_attn_kernel(const float* __restrict__ x, const float* __restrict__ bqkv,
                const float* __restrict__ bproj, float* __restrict__ out)
{
    extern __shared__ uint32_t smw[];
    uint32_t* Xw = smw + OFF_X;
    uint32_t* Qw = smw + OFF_Q;   // reused for O
    uint32_t* Kw = smw + OFF_K;
    uint32_t* Vw = smw + OFF_V;
    uint32_t* Ww = smw + OFF_W;
    uint32_t* Sw = smw + OFF_S;
    float*    Pm = (float*)(smw + OFF_PM);
    __half*   Vh = (__half*)Vw;

    const int tid = threadIdx.x, warp = tid >> 5, lane = tid & 31;
    const int g = lane >> 2, t = lane & 3;
    const int wr = warp & 1, wc = warp >> 1;
    const int mrow = wr * 32, nbase = wc * 32, sbase = wc * 16;
    const float* xw = x + (size_t)blockIdx.x * 64 * 128;

    // ---- prologue: X fp32 -> half2 smem; W chunk0 via cp.async ----
    #pragma unroll
    for (int it = 0; it < 4; ++it) {
        int idx = tid + it*256, r = idx >> 4, q = idx & 15;
        const float4* s = (const float4*)(xw + r*128 + q*8);
        float4 fa = s[0], fb = s[1];
        uint4 u = make_uint4(h2u(fa.x,fa.y), h2u(fa.z,fa.w), h2u(fb.x,fb.y), h2u(fb.z,fb.w));
        *(uint4*)(Xw + r*PXW + q*4) = u;
    }
    stageW(Ww, g_wqkvT, tid);
    __syncthreads();

    // ============ GEMM1: QKV = X @ Wqkv + b (3 chunks of 128 cols) ============
    #pragma unroll
    for (int c = 0; c < 3; ++c) {
        float acc[2][4][4];
        #pragma unroll
        for (int m = 0; m < 2; ++m)
            #pragma unroll
            for (int n = 0; n < 4; ++n)
                acc[m][n][0]=acc[m][n][1]=acc[m][n][2]=acc[m][n][3]=0.f;

        #pragma unroll
        for (int kg = 0; kg < 8; ++kg) {
            uint32_t A[8]; ldA(A, Xw + (mrow+g)*PXW + kg*8 + t, PXW);
            #pragma unroll
            for (int nt = 0; nt < 4; ++nt) {
                const uint32_t* bp = Ww + (nbase + nt*8 + g)*PWW + kg*8 + t;
                mma16(acc[0][nt], A[0],A[1],A[2],A[3], bp[0], bp[4]);
                mma16(acc[1][nt], A[4],A[5],A[6],A[7], bp[0], bp[4]);
            }
        }

        if (c < 2) {     // Q or K: store half2 rows
            uint32_t* D = (c == 0) ? Qw : Kw;
            #pragma unroll
            for (int m = 0; m < 2; ++m) {
                int r = mrow + m*16 + g;
                #pragma unroll
                for (int nt = 0; nt < 4; ++nt) {
                    int j = nbase + nt*8 + 2*t;
                    float b0 = __ldg(bqkv + c*128 + j), b1 = __ldg(bqkv + c*128 + j + 1);
                    int w = (nbase >> 1) + nt*4 + t;
                    D[r*PXW + w]     = h2u(acc[m][nt][0]+b0, acc[m][nt][1]+b1);
                    D[(r+8)*PXW + w] = h2u(acc[m][nt][2]+b0, acc[m][nt][3]+b1);
                }
            }
        } else {         // V: scatter transposed Vt[ch][tok]
            #pragma unroll
            for (int m = 0; m < 2; ++m) {
                int tok = mrow + m*16 + g;
                #pragma unroll
                for (int nt = 0; nt < 4; ++nt) {
                    int ch = nbase + nt*8 + 2*t;
                    float b0 = __ldg(bqkv + 256 + ch), b1 = __ldg(bqkv + 256 + ch + 1);
                    Vh[ch*(2*PVW) + tok]       = __float2half_rn(acc[m][nt][0]+b0);
                    Vh[(ch+1)*(2*PVW) + tok]   = __float2half_rn(acc[m][nt][1]+b1);
                    Vh[ch*(2*PVW) + tok+8]     = __float2half_rn(acc[m][nt][2]+b0);
                    Vh[(ch+1)*(2*PVW) + tok+8] = __float2half_rn(acc[m][nt][3]+b1);
                }
            }
        }
        __syncthreads();
        if (c < 2) { stageW(Ww, g_wqkvT + (c+1)*128*128, tid); __syncthreads(); }
    }

    // ============ GEMM2: S = Q @ K^T (32x16 per warp) ============
    float sacc[2][2][4];
    #pragma unroll
    for (int m = 0; m < 2; ++m)
        #pragma unroll
        for (int n = 0; n < 2; ++n)
            sacc[m][n][0]=sacc[m][n][1]=sacc[m][n][2]=sacc[m][n][3]=0.f;

    #pragma unroll
    for (int kg = 0; kg < 8; ++kg) {
        uint32_t A[8]; ldA(A, Qw + (mrow+g)*PXW + kg*8 + t, PXW);
        #pragma unroll
        for (int nt = 0; nt < 2; ++nt) {
            const uint32_t* bp = Kw + (sbase + nt*8 + g)*PXW + kg*8 + t;
            mma16(sacc[0][nt], A[0],A[1],A[2],A[3], bp[0], bp[4]);
            mma16(sacc[1][nt], A[4],A[5],A[6],A[7], bp[0], bp[4]);
        }
    }

    // ---- softmax: rows span the 4 warps with same wr ----
    const float scale = 0.08838834764831844f;
    const int bid = 1 + wr;
    float mx[2][2];
    #pragma unroll
    for (int m = 0; m < 2; ++m) {
        mx[m][0] = -1e30f; mx[m][1] = -1e30f;
        #pragma unroll
        for (int n = 0; n < 2; ++n) {
            #pragma unroll
            for (int q = 0; q < 4; ++q) sacc[m][n][q] *= scale;
            mx[m][0] = fmaxf(mx[m][0], fmaxf(sacc[m][n][0], sacc[m][n][1]));
            mx[m][1] = fmaxf(mx[m][1], fmaxf(sacc[m][n][2], sacc[m][n][3]));
        }
    }
    #pragma unroll
    for (int m = 0; m < 2; ++m)
        #pragma unroll
        for (int h = 0; h < 2; ++h) {
            mx[m][h] = fmaxf(mx[m][h], __shfl_xor_sync(~0u, mx[m][h], 1));
            mx[m][h] = fmaxf(mx[m][h], __shfl_xor_sync(~0u, mx[m][h], 2));
        }
    if (t == 0)
        #pragma unroll
        for (int m = 0; m < 2; ++m)
            #pragma unroll
            for (int h = 0; h < 2; ++h)
                Pm[(mrow + m*16 + h*8 + g)*4 + wc] = mx[m][h];
    bargrp(bid);
    #pragma unroll
    for (int m = 0; m < 2; ++m)
        #pragma unroll
        for (int h = 0; h < 2; ++h) {
            const float* p = Pm + (mrow + m*16 + h*8 + g)*4;
            mx[m][h] = fmaxf(fmaxf(p[0], p[1]), fmaxf(p[2], p[3]));
        }

    float sm[2][2] = {{0.f,0.f},{0.f,0.f}};
    #pragma unroll
    for (int m = 0; m < 2; ++m)
        #pragma unroll
        for (int n = 0; n < 2; ++n) {
            sacc[m][n][0] = __expf(sacc[m][n][0] - mx[m][0]);
            sacc[m][n][1] = __expf(sacc[m][n][1] - mx[m][0]);
            sacc[m][n][2] = __expf(sacc[m][n][2] - mx[m][1]);
            sacc[m][n][3] = __expf(sacc[m][n][3] - mx[m][1]);
            sm[m][0] += sacc[m][n][0] + sacc[m][n][1];
            sm[m][1] += sacc[m][n][2] + sacc[m][n][3];
        }
    #pragma unroll
    for (int m = 0; m < 2; ++m)
        #pragma unroll
        for (int h = 0; h < 2; ++h) {
            sm[m][h] += __shfl_xor_sync(~0u, sm[m][h], 1);
            sm[m][h] += __shfl_xor_sync(~0u, sm[m][h], 2);
        }
    if (t == 0)
        #pragma unroll
        for (int m = 0; m < 2; ++m)
            #pragma unroll
            for (int h = 0; h < 2; ++h)
                Pm[256 + (mrow + m*16 + h*8 + g)*4 + wc] = sm[m][h];
    bargrp(bid);
    float rs[2][2];
    #pragma unroll
    for (int m = 0; m < 2; ++m)
        #pragma unroll
        for (int h = 0; h < 2; ++h) {
            const float* p = Pm + 256 + (mrow + m*16 + h*8 + g)*4;
            rs[m][h] = 1.f / (p[0] + p[1] + p[2] + p[3]);
        }

    // P -> S half2 (word = col/2)
    #pragma unroll
    for (int m = 0; m < 2; ++m) {
        int r = mrow + m*16 + g;
        #pragma unroll
        for (int nt = 0; nt < 2; ++nt) {
            int w = wc*8 + nt*4 + t;
            Sw[r*PSW + w]     = h2u(sacc[m][nt][0]*rs[m][0], sacc[m][nt][1]*rs[m][0]);
            Sw[(r+8)*PSW + w] = h2u(sacc[m][nt][2]*rs[m][1], sacc[m][nt][3]*rs[m][1]);
        }
    }
    bargrp(bid);

    // ============ GEMM3: O = P @ V (32x32 per warp) ============
    float oacc[2][4][4];
    #pragma unroll
    for (int m = 0; m < 2; ++m)
        #pragma unroll
        for (int n = 0; n < 4; ++n)
            oacc[m][n][0]=oacc[m][n][1]=oacc[m][n][2]=oacc[m][n][3]=0.f;

    #pragma unroll
    for (int kg = 0; kg < 4; ++kg) {
        uint32_t A[8]; ldA(A, Sw + (mrow+g)*PSW + kg*8 + t, PSW);
        #pragma unroll
        for (int nt = 0; nt < 4; ++nt) {
            const uint32_t* bp = Vw + (nbase + nt*8 + g)*PVW + kg*8 + t;
            mma16(oacc[0][nt], A[0],A[1],A[2],A[3], bp[0], bp[4]);
            mma16(oacc[1][nt], A[4],A[5],A[6],A[7], bp[0], bp[4]);
        }
    }

    // O -> Qw (half2 rows)
    #pragma unroll
    for (int m = 0; m < 2; ++m) {
        int r = mrow + m*16 + g;
        #pragma unroll
        for (int nt = 0; nt < 4; ++nt) {
            int w = (nbase >> 1) + nt*4 + t;
            Qw[r*PXW + w]     = h2u(oacc[m][nt][0], oacc[m][nt][1]);
            Qw[(r+8)*PXW + w] = h2u(oacc[m][nt][2], oacc[m][nt][3]);
        }
    }
    __syncthreads();                       // all S reads + O writes done
    stageW(Ww, g_wprojT, tid);             // overwrites S/Pm region (dead)
    __syncthreads();

    // ============ GEMM4: out = O @ Wproj + b ============
    float acc[2][4][4];
    #pragma unroll
    for (int m = 0; m < 2; ++m)
        #pragma unroll
        for (int n = 0; n < 4; ++n)
            acc[m][n][0]=acc[m][n][1]=acc[m][n][2]=acc[m][n][3]=0.f;

    #pragma unroll
    for (int kg = 0; kg < 8; ++kg) {
        uint32_t A[8]; ldA(A, Qw + (mrow+g)*PXW + kg*8 + t, PXW);
        #pragma unroll
        for (int nt = 0; nt < 4; ++nt) {
            const uint32_t* bp = Ww + (nbase + nt*8 + g)*PWW + kg*8 + t;
            mma16(acc[0][nt], A[0],A[1],A[2],A[3], bp[0], bp[4]);
            mma16(acc[1][nt], A[4],A[5],A[6],A[7], bp[0], bp[4]);
        }
    }

    float* outw = out + (size_t)blockIdx.x * 64 * 128;
    #pragma unroll
    for (int m = 0; m < 2; ++m) {
        int r = mrow + m*16 + g;
        #pragma unroll
        for (int nt = 0; nt < 4; ++nt) {
            int j = nbase + nt*8 + 2*t;
            float b0 = __ldg(bproj + j), b1 = __ldg(bproj + j + 1);
            *(float2*)(outw + r*128 + j)     = make_float2(acc[m][nt][0]+b0, acc[m][nt][1]+b1);
            *(float2*)(outw + (r+8)*128 + j) = make_float2(acc[m][nt][2]+b0, acc[m][nt][3]+b1);
        }
    }
}

extern "C" void kernel_launch(void* const* d_in, const int* in_sizes, int n_in,
                              void* d_out, int out_size)
{
    const float* x     = (const float*)d_in[0];
    const float* wqkv  = (const float*)d_in[1];
    const float* bqkv  = (const float*)d_in[2];
    const float* wproj = (const float*)d_in[3];
    const float* bproj = (const float*)d_in[4];
    float* out = (float*)d_out;

    const int nwin = in_sizes[0] / (64 * 128);  // 4096

    prep_w<<<512, 128>>>(wqkv, wproj);
    cudaFuncSetAttribute(win_attn_kernel,
                         cudaFuncAttributeMaxDynamicSharedMemorySize, SMEM_BYTES);
    win_attn_kernel<<<nwin, 256, SMEM_BYTES>>>(x, bqkv, bproj, out);
}

// round 12
// speedup vs baseline: 1.9650x; 1.0478x over previous
#include <cuda_runtime.h>
#include <cuda_fp16.h>
#include <cstdint>

// WindowAttention: 4096 x 64 x 128, fp32 I/O. fp16 operands, fp32 accumulate,
// mma.m16n8k16. R12: 128 thr/CTA, 4 warps, 64x32 warp tiles (weight bytes
// cross the smem crossbar exactly ONCE). 2 CTAs/SM. (tcgen05 rejected by
// toolchain: PTX targets sm_103, accel features unavailable.)

#define PXW 68   // X/Q/K/O pitch in words
#define PSW 36   // S pitch
#define PVW 36   // Vt pitch
#define PWW 68   // W pitch

#define OFF_X 0
#define OFF_Q (64*PXW)
#define OFF_K (2*64*PXW)
#define OFF_V (3*64*PXW)
#define OFF_W (OFF_V + 128*PVW)
#define OFF_S OFF_W                 // S aliases W
#define OFF_PM (OFF_S + 64*PSW)
#define SMEM_WORDS (OFF_W + 128*PWW)
#define SMEM_BYTES (SMEM_WORDS*4)   // 105472 -> 2 CTAs/SM

__device__ __align__(16) __half g_wqkvT[384*128];
__device__ __align__(16) __half g_wprojT[128*128];

__global__ void prep_w(const float* __restrict__ wqkv, const float* __restrict__ wproj) {
    int n = blockIdx.x, k = threadIdx.x;
    if (n < 384) g_wqkvT[n*128+k] = __float2half_rn(wqkv[k*384+n]);
    else         g_wprojT[(n-384)*128+k] = __float2half_rn(wproj[k*128+(n-384)]);
}

__device__ __forceinline__ uint32_t h2u(float a, float b) {
    __half2 h = __floats2half2_rn(a, b);
    return *reinterpret_cast<uint32_t*>(&h);
}
__device__ __forceinline__ void mma16(float acc[4], uint32_t a0, uint32_t a1,
                                      uint32_t a2, uint32_t a3, uint32_t b0, uint32_t b1) {
    asm volatile(
        "mma.sync.aligned.m16n8k16.row.col.f32.f16.f16.f32 "
        "{%0,%1,%2,%3}, {%4,%5,%6,%7}, {%8,%9}, {%0,%1,%2,%3};\n"
        : "+f"(acc[0]), "+f"(acc[1]), "+f"(acc[2]), "+f"(acc[3])
        : "r"(a0), "r"(a1), "r"(a2), "r"(a3), "r"(b0), "r"(b1));
}
// one m16 A fragment at word ptr p (= base + row*pitch + kg*8 + t)
__device__ __forceinline__ void ldA4(uint32_t a[4], const uint32_t* p, int pitch) {
    a[0]=p[0]; a[1]=p[8*pitch]; a[2]=p[4]; a[3]=p[8*pitch+4];
}
// stage full 128x128 fp16 chunk [n][k] -> smem pitch PWW via cp.async 16B
__device__ __forceinline__ void stageW(uint32_t* Ww, const __half* __restrict__ src, int tid) {
    uint32_t base = (uint32_t)__cvta_generic_to_shared(Ww);
    #pragma unroll
    for (int it = 0; it < 16; ++it) {
        int idx = tid + it*128, n = idx >> 4, q = idx & 15;
        uint32_t dst = base + (uint32_t)(n*PWW + q*4)*4u;
        asm volatile("cp.async.ca.shared.global [%0], [%1], 16;"
                     :: "r"(dst), "l"(src + n*128 + q*8) : "memory");
    }
    asm volatile("cp.async.commit_group;\n\tcp.async.wait_group 0;" ::: "memory");
}

__global__ void __launch_bounds__(128, 2)
win_attn_kernel(const float* __restrict__ x, const float* __restrict__ bqkv,
                const float* __restrict__ bproj, float* __restrict__ out)
{
    extern __shared__ uint32_t smw[];
    uint32_t* Xw = smw + OFF_X;
    uint32_t* Qw = smw + OFF_Q;   // reused for O
    uint32_t* Kw = smw + OFF_K;
    uint32_t* Vw = smw + OFF_V;
    uint32_t* Ww = smw + OFF_W;
    uint32_t* Sw = smw + OFF_S;
    float*    Pm = (float*)(smw + OFF_PM);
    __half*   Vh = (__half*)Vw;

    const int tid = threadIdx.x, warp = tid >> 5, lane = tid & 31;
    const int g = lane >> 2, t = lane & 3;
    const int wc = warp;                    // 0..3: 32-col strip
    const int nbase = wc * 32, sbase = wc * 16;
    const float* xw = x + (size_t)blockIdx.x * 64 * 128;

    // ---- prologue: X fp32 -> half2 smem; W chunk0 ----
    #pragma unroll
    for (int it = 0; it < 8; ++it) {
        int idx = tid + it*128, r = idx >> 4, q = idx & 15;
        const float4* s = (const float4*)(xw + r*128 + q*8);
        float4 fa = s[0], fb = s[1];
        uint4 u = make_uint4(h2u(fa.x,fa.y), h2u(fa.z,fa.w), h2u(fb.x,fb.y), h2u(fb.z,fb.w));
        *(uint4*)(Xw + r*PXW + q*4) = u;
    }
    stageW(Ww, g_wqkvT, tid);
    __syncthreads();

    // ============ GEMM1: QKV = X @ Wqkv + b (3 chunks of 128 cols) ============
    #pragma unroll
    for (int c = 0; c < 3; ++c) {
        float acc[4][4][4];                 // [m-tile][n-tile][frag]
        #pragma unroll
        for (int m = 0; m < 4; ++m)
            #pragma unroll
            for (int n = 0; n < 4; ++n)
                acc[m][n][0]=acc[m][n][1]=acc[m][n][2]=acc[m][n][3]=0.f;

        #pragma unroll
        for (int kg = 0; kg < 8; ++kg) {
            uint32_t A[16];
            #pragma unroll
            for (int m = 0; m < 4; ++m)
                ldA4(A + m*4, Xw + (m*16+g)*PXW + kg*8 + t, PXW);
            #pragma unroll
            for (int nt = 0; nt < 4; ++nt) {
                const uint32_t* bp = Ww + (nbase + nt*8 + g)*PWW + kg*8 + t;
                uint32_t b0 = bp[0], b1 = bp[4];
                #pragma unroll
                for (int m = 0; m < 4; ++m)
                    mma16(acc[m][nt], A[m*4],A[m*4+1],A[m*4+2],A[m*4+3], b0, b1);
            }
        }

        if (c < 2) {     // Q or K: half2 rows
            uint32_t* D = (c == 0) ? Qw : Kw;
            #pragma unroll
            for (int m = 0; m < 4; ++m) {
                int r = m*16 + g;
                #pragma unroll
                for (int nt = 0; nt < 4; ++nt) {
                    int j = nbase + nt*8 + 2*t;
                    float b0 = __ldg(bqkv + c*128 + j), b1 = __ldg(bqkv + c*128 + j + 1);
                    int w = (nbase >> 1) + nt*4 + t;
                    D[r*PXW + w]     = h2u(acc[m][nt][0]+b0, acc[m][nt][1]+b1);
                    D[(r+8)*PXW + w] = h2u(acc[m][nt][2]+b0, acc[m][nt][3]+b1);
                }
            }
        } else {         // V: transposed scatter Vt[ch][tok]
            #pragma unroll
            for (int m = 0; m < 4; ++m) {
                int tok = m*16 + g;
                #pragma unroll
                for (int nt = 0; nt < 4; ++nt) {
                    int ch = nbase + nt*8 + 2*t;
                    float b0 = __ldg(bqkv + 256 + ch), b1 = __ldg(bqkv + 256 + ch + 1);
                    Vh[ch*(2*PVW) + tok]       = __float2half_rn(acc[m][nt][0]+b0);
                    Vh[(ch+1)*(2*PVW) + tok]   = __float2half_rn(acc[m][nt][1]+b1);
                    Vh[ch*(2*PVW) + tok+8]     = __float2half_rn(acc[m][nt][2]+b0);
                    Vh[(ch+1)*(2*PVW) + tok+8] = __float2half_rn(acc[m][nt][3]+b1);
                }
            }
        }
        __syncthreads();
        if (c < 2) { stageW(Ww, g_wqkvT + (c+1)*128*128, tid); __syncthreads(); }
    }

    // ============ GEMM2: S = Q @ K^T (64x16 per warp) ============
    float sacc[4][2][4];
    #pragma unroll
    for (int m = 0; m < 4; ++m)
        #pragma unroll
        for (int n = 0; n < 2; ++n)
            sacc[m][n][0]=sacc[m][n][1]=sacc[m][n][2]=sacc[m][n][3]=0.f;

    #pragma unroll
    for (int kg = 0; kg < 8; ++kg) {
        uint32_t A[16];
        #pragma unroll
        for (int m = 0; m < 4; ++m)
            ldA4(A + m*4, Qw + (m*16+g)*PXW + kg*8 + t, PXW);
        #pragma unroll
        for (int nt = 0; nt < 2; ++nt) {
            const uint32_t* bp = Kw + (sbase + nt*8 + g)*PXW + kg*8 + t;
            uint32_t b0 = bp[0], b1 = bp[4];
            #pragma unroll
            for (int m = 0; m < 4; ++m)
                mma16(sacc[m][nt], A[m*4],A[m*4+1],A[m*4+2],A[m*4+3], b0, b1);
        }
    }

    // ---- softmax: each row spans all 4 warps (16 cols each) ----
    const float scale = 0.08838834764831844f;
    float mx[4][2];
    #pragma unroll
    for (int m = 0; m < 4; ++m) {
        mx[m][0] = -1e30f; mx[m][1] = -1e30f;
        #pragma unroll
        for (int n = 0; n < 2; ++n) {
            #pragma unroll
            for (int q = 0; q < 4; ++q) sacc[m][n][q] *= scale;
            mx[m][0] = fmaxf(mx[m][0], fmaxf(sacc[m][n][0], sacc[m][n][1]));
            mx[m][1] = fmaxf(mx[m][1], fmaxf(sacc[m][n][2], sacc[m][n][3]));
        }
    }
    #pragma unroll
    for (int m = 0; m < 4; ++m)
        #pragma unroll
        for (int h = 0; h < 2; ++h) {
            mx[m][h] = fmaxf(mx[m][h], __shfl_xor_sync(~0u, mx[m][h], 1));
            mx[m][h] = fmaxf(mx[m][h], __shfl_xor_sync(~0u, mx[m][h], 2));
        }
    if (t == 0)
        #pragma unroll
        for (int m = 0; m < 4; ++m)
            #pragma unroll
            for (int h = 0; h < 2; ++h)
                Pm[(m*16 + h*8 + g)*4 + wc] = mx[m][h];
    __syncthreads();
    #pragma unroll
    for (int m = 0; m < 4; ++m)
        #pragma unroll
        for (int h = 0; h < 2; ++h) {
            const float* p = Pm + (m*16 + h*8 + g)*4;
            mx[m][h] = fmaxf(fmaxf(p[0], p[1]), fmaxf(p[2], p[3]));
        }

    float sm[4][2];
    #pragma unroll
    for (int m = 0; m < 4; ++m) { sm[m][0] = 0.f; sm[m][1] = 0.f; }
    #pragma unroll
    for (int m = 0; m < 4; ++m)
        #pragma unroll
        for (int n = 0; n < 2; ++n) {
            sacc[m][n][0] = __expf(sacc[m][n][0] - mx[m][0]);
            sacc[m][n][1] = __expf(sacc[m][n][1] - mx[m][0]);
            sacc[m][n][2] = __expf(sacc[m][n][2] - mx[m][1]);
            sacc[m][n][3] = __expf(sacc[m][n][3] - mx[m][1]);
            sm[m][0] += sacc[m][n][0] + sacc[m][n][1];
            sm[m][1] += sacc[m][n][2] + sacc[m][n][3];
        }
    #pragma unroll
    for (int m = 0; m < 4; ++m)
        #pragma unroll
        for (int h = 0; h < 2; ++h) {
            sm[m][h] += __shfl_xor_sync(~0u, sm[m][h], 1);
            sm[m][h] += __shfl_xor_sync(~0u, sm[m][h], 2);
        }
    if (t == 0)
        #pragma unroll
        for (int m = 0; m < 4; ++m)
            #pragma unroll
            for (int h = 0; h < 2; ++h)
                Pm[256 + (m*16 + h*8 + g)*4 + wc] = sm[m][h];
    __syncthreads();
    float rs[4][2];
    #pragma unroll
    for (int m = 0; m < 4; ++m)
        #pragma unroll
        for (int h = 0; h < 2; ++h) {
            const float* p = Pm + 256 + (m*16 + h*8 + g)*4;
            rs[m][h] = 1.f / (p[0] + p[1] + p[2] + p[3]);
        }

    // P -> S half2
    #pragma unroll
    for (int m = 0; m < 4; ++m) {
        int r = m*16 + g;
        #pragma unroll
        for (int nt = 0; nt < 2; ++nt) {
            int w = wc*8 + nt*4 + t;
            Sw[r*PSW + w]     = h2u(sacc[m][nt][0]*rs[m][0], sacc[m][nt][1]*rs[m][0]);
            Sw[(r+8)*PSW + w] = h2u(sacc[m][nt][2]*rs[m][1], sacc[m][nt][3]*rs[m][1]);
        }
    }
    __syncthreads();

    // ============ GEMM3: O = P @ Vt (64x32 per warp) ============
    float oacc[4][4][4];
    #pragma unroll
    for (int m = 0; m < 4; ++m)
        #pragma unroll
        for (int n = 0; n < 4; ++n)
            oacc[m][n][0]=oacc[m][n][1]=oacc[m][n][2]=oacc[m][n][3]=0.f;

    #pragma unroll
    for (int kg = 0; kg < 4; ++kg) {
        uint32_t A[16];
        #pragma unroll
        for (int m = 0; m < 4; ++m)
            ldA4(A + m*4, Sw + (m*16+g)*PSW + kg*8 + t, PSW);
        #pragma unroll
        for (int nt = 0; nt < 4; ++nt) {
            const uint32_t* bp = Vw + (nbase + nt*8 + g)*PVW + kg*8 + t;
            uint32_t b0 = bp[0], b1 = bp[4];
            #pragma unroll
            for (int m = 0; m < 4; ++m)
                mma16(oacc[m][nt], A[m*4],A[m*4+1],A[m*4+2],A[m*4+3], b0, b1);
        }
    }

    // O -> Qw (half2 rows)
    #pragma unroll
    for (int m = 0; m < 4; ++m) {
        int r = m*16 + g;
        #pragma unroll
        for (int nt = 0; nt < 4; ++nt) {
            int w = (nbase >> 1) + nt*4 + t;
            Qw[r*PXW + w]     = h2u(oacc[m][nt][0], oacc[m][nt][1]);
            Qw[(r+8)*PXW + w] = h2u(oacc[m][nt][2], oacc[m][nt][3]);
        }
    }
    __syncthreads();                   // all S reads + O writes done
    stageW(Ww, g_wprojT, tid);         // overwrites S/Pm region (dead)
    __syncthreads();

    // ============ GEMM4: out = O @ Wproj + b ============
    float acc[4][4][4];
    #pragma unroll
    for (int m = 0; m < 4; ++m)
        #pragma unroll
        for (int n = 0; n < 4; ++n)
            acc[m][n][0]=acc[m][n][1]=acc[m][n][2]=acc[m][n][3]=0.f;

    #pragma unroll
    for (int kg = 0; kg < 8; ++kg) {
        uint32_t A[16];
        #pragma unroll
        for (int m = 0; m < 4; ++m)
            ldA4(A + m*4, Qw + (m*16+g)*PXW + kg*8 + t, PXW);
        #pragma unroll
        for (int nt = 0; nt < 4; ++nt) {
            const uint32_t* bp = Ww + (nbase + nt*8 + g)*PWW + kg*8 + t;
            uint32_t b0 = bp[0], b1 = bp[4];
            #pragma unroll
            for (int m = 0; m < 4; ++m)
                mma16(acc[m][nt], A[m*4],A[m*4+1],A[m*4+2],A[m*4+3], b0, b1);
        }
    }

    float* outw = out + (size_t)blockIdx.x * 64 * 128;
    #pragma unroll
    for (int m = 0; m < 4; ++m) {
        int r = m*16 + g;
        #pragma unroll
        for (int nt = 0; nt < 4; ++nt) {
            int j = nbase + nt*8 + 2*t;
            float b0 = __ldg(bproj + j), b1 = __ldg(bproj + j + 1);
            *(float2*)(outw + r*128 + j)     = make_float2(acc[m][nt][0]+b0, acc[m][nt][1]+b1);
            *(float2*)(outw + (r+8)*128 + j) = make_float2(acc[m][nt][2]+b0, acc[m][nt][3]+b1);
        }
    }
}

extern "C" void kernel_launch(void* const* d_in, const int* in_sizes, int n_in,
                              void* d_out, int out_size)
{
    const float* x     = (const float*)d_in[0];
    const float* wqkv  = (const float*)d_in[1];
    const float* bqkv  = (const float*)d_in[2];
    const float* wproj = (const float*)d_in[3];
    const float* bproj = (const float*)d_in[4];
    float* out = (float*)d_out;

    const int nwin = in_sizes[0] / (64 * 128);   // 4096

    prep_w<<<512, 128>>>(wqkv, wproj);
    cudaFuncSetAttribute(win_attn_kernel,
                         cudaFuncAttributeMaxDynamicSharedMemorySize, SMEM_BYTES);
    win_attn_kernel<<<nwin, 128, SMEM_BYTES>>>(x, bqkv, bproj, out);
}